// round 6
// baseline (speedup 1.0000x reference)
#include <cuda_runtime.h>

// Analytic reduction (see prior rounds): per contiguous 8-float group,
//   c_i = cos(x_i + theta_i)
//   out[j] = prod_{i=0..j} c_i   (j=1..7),   out[0] = prod_{i=1..7} c_i
//
// Best measured shape (R4): two threads per group (one float4 each), pair
// exchange via shfl_xor, block=1024, grid=128 -> one flat wave, occ ~48%.
// This round re-tests that shape + streaming stores.
// |phi| <~ 7 so __cosf (MUFU fast path) abs err ~1e-6, far under 1e-3.

__global__ __launch_bounds__(1024)
void quantum_heads_kernel(const float* __restrict__ x,
                          const float* __restrict__ theta,
                          float* __restrict__ out,
                          int nquads)   // nquads = 2 * ngroups
{
    int tid = blockIdx.x * blockDim.x + threadIdx.x;
    if (tid >= nquads) return;

    int half = tid & 1;   // 0 = first 4 lanes of group, 1 = last 4

    const float4* tp = reinterpret_cast<const float4*>(theta);
    float4 t = __ldg(tp + half);

    const float4* xp = reinterpret_cast<const float4*>(x);
    float4 v = __ldg(xp + tid);

    float c0 = __cosf(v.x + t.x);
    float c1 = __cosf(v.y + t.y);
    float c2 = __cosf(v.z + t.z);
    float c3 = __cosf(v.w + t.w);

    float p01  = c0 * c1;
    float p012 = p01 * c2;
    float full = p012 * c3;          // product of this thread's 4 cosines

    // exchange 4-way products with pair partner (lanes 2g, 2g+1 adjacent)
    float other = __shfl_xor_sync(0xFFFFFFFFu, full, 1);

    float4 o;
    if (half == 0) {
        // outputs 0..3:  out0 = c1*c2*c3 * (c4..c7),  then prefixes
        o.x = (c1 * c2) * (c3 * other);
        o.y = p01;
        o.z = p012;
        o.w = full;
    } else {
        // outputs 4..7: prefixes continued with P3 = c0..c3 from partner
        o.x = other * c0;
        o.y = other * p01;
        o.z = other * p012;
        o.w = other * full;
    }

    __stcs(reinterpret_cast<float4*>(out) + tid, o);
}

extern "C" void kernel_launch(void* const* d_in, const int* in_sizes, int n_in,
                              void* d_out, int out_size)
{
    const float* x     = (const float*)d_in[0];
    const float* theta = (const float*)d_in[1];
    float* out         = (float*)d_out;

    int nquads  = in_sizes[0] / 4;   // one thread per float4 (half group)
    int threads = 1024;
    int blocks  = (nquads + threads - 1) / threads;   // 128 for the bench shape
    quantum_heads_kernel<<<blocks, threads>>>(x, theta, out, nquads);
}

// round 7
// speedup vs baseline: 1.0047x; 1.0047x over previous
#include <cuda_runtime.h>

// Analytic reduction (see prior rounds): per contiguous 8-float group,
//   c_i = cos(x_i + theta_i)
//   out[j] = prod_{i=0..j} c_i   (j=1..7),   out[0] = prod_{i=1..7} c_i
//
// Best measured configuration (R4, dur_us=6.56): two threads per group (one
// float4 each), pair exchange via shfl_xor, block=1024, grid=128 (one flat
// wave, occ ~48%), PLAIN STG.128 stores — the __stcs variant (R6) measured
// slower end-to-end, plausibly from evict-first writeback lengthening the
// store drain the graph-replay interval observes. This is R4 byte-for-byte.
// |phi| <~ 7 so __cosf (MUFU fast path) abs err ~1e-6, far under 1e-3.

__global__ __launch_bounds__(1024)
void quantum_heads_kernel(const float* __restrict__ x,
                          const float* __restrict__ theta,
                          float* __restrict__ out,
                          int nquads)   // nquads = 2 * ngroups
{
    int tid = blockIdx.x * blockDim.x + threadIdx.x;
    if (tid >= nquads) return;

    int half = tid & 1;   // 0 = first 4 lanes of group, 1 = last 4

    const float4* tp = reinterpret_cast<const float4*>(theta);
    float4 t = __ldg(tp + half);

    const float4* xp = reinterpret_cast<const float4*>(x);
    float4 v = __ldg(xp + tid);

    float c0 = __cosf(v.x + t.x);
    float c1 = __cosf(v.y + t.y);
    float c2 = __cosf(v.z + t.z);
    float c3 = __cosf(v.w + t.w);

    float p01  = c0 * c1;
    float p012 = p01 * c2;
    float full = p012 * c3;          // product of this thread's 4 cosines

    // exchange 4-way products with pair partner (lanes 2g, 2g+1 adjacent)
    float other = __shfl_xor_sync(0xFFFFFFFFu, full, 1);

    float4 o;
    if (half == 0) {
        // outputs 0..3:  out0 = c1*c2*c3 * (c4..c7),  then prefixes
        o.x = (c1 * c2) * (c3 * other);
        o.y = p01;
        o.z = p012;
        o.w = full;
    } else {
        // outputs 4..7: prefixes continued with P3 = c0..c3 from partner
        o.x = other * c0;
        o.y = other * p01;
        o.z = other * p012;
        o.w = other * full;
    }

    reinterpret_cast<float4*>(out)[tid] = o;
}

extern "C" void kernel_launch(void* const* d_in, const int* in_sizes, int n_in,
                              void* d_out, int out_size)
{
    const float* x     = (const float*)d_in[0];
    const float* theta = (const float*)d_in[1];
    float* out         = (float*)d_out;

    int nquads  = in_sizes[0] / 4;   // one thread per float4 (half group)
    int threads = 1024;
    int blocks  = (nquads + threads - 1) / threads;   // 128 for the bench shape
    quantum_heads_kernel<<<blocks, threads>>>(x, theta, out, nquads);
}